// round 4
// baseline (speedup 1.0000x reference)
#include <cuda_runtime.h>
#include <math.h>

#define BATCH 4
#define LSEQ 2048
#define NHEAD 16
#define DKH 64
#define NFEAT 1024
#define MTOT (BATCH*LSEQ)

// Scratch (allocation-free rule: __device__ globals). 128 MB total.
__device__ float g_Q[MTOT*NFEAT];
__device__ float g_K[MTOT*NFEAT];
__device__ float g_V[MTOT*NFEAT];
__device__ float g_A[MTOT*NFEAT];

// ---------------------------------------------------------------------------
// 128x128x16 register-tiled SGEMM, 256 threads, 8x8 per-thread tile.
// QKV_LAYOUT=1 scatters output into [B,H,L,Dk] for coalesced attention loads.
// ---------------------------------------------------------------------------
template<int QKV_LAYOUT>
__global__ __launch_bounds__(256)
void sgemm128(const float* __restrict__ A, const float* __restrict__ B,
              const float* __restrict__ bias, float* __restrict__ C,
              int M, int N, int K) {
    __shared__ float As[16][132];   // transposed A tile, padded
    __shared__ float Bs[16][128];
    const int tid = threadIdx.x;
    const int m0 = blockIdx.y * 128;
    const int n0 = blockIdx.x * 128;
    const int tr = tid >> 4;          // 0..15 row group
    const int tc = tid & 15;          // 0..15 col group
    const int aRow = tid >> 2;        // 0..63
    const int aCol = (tid & 3) << 2;  // 0,4,8,12
    const int bRow = tid >> 5;        // 0..7
    const int bCol = (tid & 31) << 2; // 0..124

    float acc[8][8];
#pragma unroll
    for (int i = 0; i < 8; i++)
#pragma unroll
        for (int j = 0; j < 8; j++) acc[i][j] = 0.f;

    for (int kk = 0; kk < K; kk += 16) {
#pragma unroll
        for (int r = 0; r < 2; r++) {
            float4 v = *(const float4*)(A + (size_t)(m0 + aRow + 64*r)*K + kk + aCol);
            As[aCol+0][aRow+64*r] = v.x;
            As[aCol+1][aRow+64*r] = v.y;
            As[aCol+2][aRow+64*r] = v.z;
            As[aCol+3][aRow+64*r] = v.w;
        }
#pragma unroll
        for (int r = 0; r < 2; r++) {
            *(float4*)&Bs[bRow+8*r][bCol] =
                *(const float4*)(B + (size_t)(kk + bRow + 8*r)*N + n0 + bCol);
        }
        __syncthreads();
#pragma unroll
        for (int k = 0; k < 16; k++) {
            float ra[8], rb[8];
            *(float4*)&ra[0] = *(float4*)&As[k][tr*8];
            *(float4*)&ra[4] = *(float4*)&As[k][tr*8+4];
            *(float4*)&rb[0] = *(float4*)&Bs[k][tc*8];
            *(float4*)&rb[4] = *(float4*)&Bs[k][tc*8+4];
#pragma unroll
            for (int i = 0; i < 8; i++)
#pragma unroll
                for (int j = 0; j < 8; j++)
                    acc[i][j] = fmaf(ra[i], rb[j], acc[i][j]);
        }
        __syncthreads();
    }

#pragma unroll
    for (int i = 0; i < 8; i++) {
        int m = m0 + tr*8 + i;
#pragma unroll
        for (int j4 = 0; j4 < 2; j4++) {
            int n = n0 + tc*8 + j4*4;
            float4 bv = *(const float4*)(bias + n);
            float4 o;
            o.x = acc[i][j4*4+0] + bv.x;
            o.y = acc[i][j4*4+1] + bv.y;
            o.z = acc[i][j4*4+2] + bv.z;
            o.w = acc[i][j4*4+3] + bv.w;
            if (QKV_LAYOUT) {
                int b = m >> 11, l = m & 2047;
                int h = n >> 6, d = n & 63;
                *(float4*)(C + ((size_t)((b*NHEAD + h)*LSEQ + l))*DKH + d) = o;
            } else {
                *(float4*)(C + (size_t)m*N + n) = o;
            }
        }
    }
}

// ---------------------------------------------------------------------------
// Flash-style attention: one block per (64-query tile, b*h).
// 64x64 S tiles, online softmax, state in registers.
// S phase:  thread owns rows {ty+16i}, cols {tx+16j}  (conflict-free smem)
// PV phase: thread owns rows {ty+16i}, dims {4tx+j}   (float4 V reads)
// ---------------------------------------------------------------------------
__global__ __launch_bounds__(256)
void attn64(const float* __restrict__ Q, const float* __restrict__ K,
            const float* __restrict__ V, float* __restrict__ O) {
    extern __shared__ float sm[];
    float* Qs = sm;               // [64][68]
    float* Ks = Qs + 64*68;       // [64][68]
    float* Vs = Ks + 64*68;       // [64][64]
    float* Ps = Vs + 64*64;       // [64][68]

    const int tid = threadIdx.x;
    const int tx = tid & 15, ty = tid >> 4;
    const int bh = blockIdx.y;
    const int q0 = blockIdx.x * 64;
    const float* Qg = Q + (size_t)bh * LSEQ * DKH;
    const float* Kg = K + (size_t)bh * LSEQ * DKH;
    const float* Vg = V + (size_t)bh * LSEQ * DKH;

    // Load Q tile, fold in 1/sqrt(Dk)
#pragma unroll
    for (int rr = 0; rr < 4; rr++) {
        int row = rr*16 + ty;
        float4 v = *(const float4*)(Qg + (size_t)(q0+row)*DKH + tx*4);
        v.x *= 0.125f; v.y *= 0.125f; v.z *= 0.125f; v.w *= 0.125f;
        *(float4*)&Qs[row*68 + tx*4] = v;
    }

    float m_i[4], l_i[4], acc[4][4];
#pragma unroll
    for (int i = 0; i < 4; i++) {
        m_i[i] = -1e30f; l_i[i] = 0.f;
#pragma unroll
        for (int j = 0; j < 4; j++) acc[i][j] = 0.f;
    }
    __syncthreads();

    for (int t = 0; t < LSEQ/64; t++) {
        const int k0 = t*64;
#pragma unroll
        for (int rr = 0; rr < 4; rr++) {
            int row = rr*16 + ty;
            *(float4*)&Ks[row*68 + tx*4] =
                *(const float4*)(Kg + (size_t)(k0+row)*DKH + tx*4);
            *(float4*)&Vs[row*64 + tx*4] =
                *(const float4*)(Vg + (size_t)(k0+row)*DKH + tx*4);
        }
        __syncthreads();

        // ---- S = Q K^T (scaled) ----
        float s[4][4];
#pragma unroll
        for (int i = 0; i < 4; i++)
#pragma unroll
            for (int j = 0; j < 4; j++) s[i][j] = 0.f;

#pragma unroll
        for (int d4 = 0; d4 < 16; d4++) {
            float4 q4[4], k4[4];
#pragma unroll
            for (int i = 0; i < 4; i++) q4[i] = *(float4*)&Qs[(ty+16*i)*68 + d4*4];
#pragma unroll
            for (int j = 0; j < 4; j++) k4[j] = *(float4*)&Ks[(tx+16*j)*68 + d4*4];
#pragma unroll
            for (int i = 0; i < 4; i++)
#pragma unroll
                for (int j = 0; j < 4; j++) {
                    s[i][j] = fmaf(q4[i].x, k4[j].x, s[i][j]);
                    s[i][j] = fmaf(q4[i].y, k4[j].y, s[i][j]);
                    s[i][j] = fmaf(q4[i].z, k4[j].z, s[i][j]);
                    s[i][j] = fmaf(q4[i].w, k4[j].w, s[i][j]);
                }
        }

        // ---- online softmax (rows reduced over 16-lane tx groups) ----
#pragma unroll
        for (int i = 0; i < 4; i++) {
            float rmax = fmaxf(fmaxf(s[i][0], s[i][1]), fmaxf(s[i][2], s[i][3]));
#pragma unroll
            for (int msk = 1; msk < 16; msk <<= 1)
                rmax = fmaxf(rmax, __shfl_xor_sync(0xffffffffu, rmax, msk));
            float mnew = fmaxf(m_i[i], rmax);
            float corr = __expf(m_i[i] - mnew);
            m_i[i] = mnew;
            float rsum = 0.f;
#pragma unroll
            for (int j = 0; j < 4; j++) {
                float p = __expf(s[i][j] - mnew);
                s[i][j] = p;
                rsum += p;
            }
#pragma unroll
            for (int msk = 1; msk < 16; msk <<= 1)
                rsum += __shfl_xor_sync(0xffffffffu, rsum, msk);
            l_i[i] = l_i[i]*corr + rsum;
#pragma unroll
            for (int j = 0; j < 4; j++) acc[i][j] *= corr;
#pragma unroll
            for (int j = 0; j < 4; j++)
                Ps[(ty+16*i)*68 + tx + 16*j] = s[i][j];
        }
        __syncthreads();

        // ---- O += P V ----
#pragma unroll
        for (int kc4 = 0; kc4 < 16; kc4++) {
            float p4[4][4];
#pragma unroll
            for (int i = 0; i < 4; i++)
                *(float4*)&p4[i][0] = *(float4*)&Ps[(ty+16*i)*68 + kc4*4];
#pragma unroll
            for (int u = 0; u < 4; u++) {
                float4 v4 = *(float4*)&Vs[(kc4*4+u)*64 + tx*4];
#pragma unroll
                for (int i = 0; i < 4; i++) {
                    float p = p4[i][u];
                    acc[i][0] = fmaf(p, v4.x, acc[i][0]);
                    acc[i][1] = fmaf(p, v4.y, acc[i][1]);
                    acc[i][2] = fmaf(p, v4.z, acc[i][2]);
                    acc[i][3] = fmaf(p, v4.w, acc[i][3]);
                }
            }
        }
        __syncthreads();
    }

    // write O back in [B, L, H*Dk] layout (attn output before Wo)
    const int b = bh >> 4, h = bh & 15;
#pragma unroll
    for (int i = 0; i < 4; i++) {
        float inv = 1.f / l_i[i];
        int row = q0 + ty + 16*i;
        float4 o;
        o.x = acc[i][0]*inv; o.y = acc[i][1]*inv;
        o.z = acc[i][2]*inv; o.w = acc[i][3]*inv;
        *(float4*)(O + ((size_t)(b*LSEQ + row))*NFEAT + h*DKH + tx*4) = o;
    }
}

// ---------------------------------------------------------------------------
extern "C" void kernel_launch(void* const* d_in, const int* in_sizes, int n_in,
                              void* d_out, int out_size) {
    const float* query = (const float*)d_in[0];
    const float* key_  = (const float*)d_in[1];
    const float* value = (const float*)d_in[2];
    const float* Wq = (const float*)d_in[3];
    const float* bq = (const float*)d_in[4];
    const float* Wk = (const float*)d_in[5];
    const float* bk = (const float*)d_in[6];
    const float* Wv = (const float*)d_in[7];
    const float* bv = (const float*)d_in[8];
    const float* Wo = (const float*)d_in[9];
    const float* bo = (const float*)d_in[10];
    float* out = (float*)d_out;

    float *qP, *kP, *vP, *aP;
    cudaGetSymbolAddress((void**)&qP, g_Q);
    cudaGetSymbolAddress((void**)&kP, g_K);
    cudaGetSymbolAddress((void**)&vP, g_V);
    cudaGetSymbolAddress((void**)&aP, g_A);

    dim3 gGemm(NFEAT/128, MTOT/128);   // (8, 64)
    sgemm128<1><<<gGemm, 256>>>(query, Wq, bq, qP, MTOT, NFEAT, 1024);
    sgemm128<1><<<gGemm, 256>>>(key_,  Wk, bk, kP, MTOT, NFEAT, 1024);
    sgemm128<1><<<gGemm, 256>>>(value, Wv, bv, vP, MTOT, NFEAT, 1024);

    const int smem = (64*68 + 64*68 + 64*64 + 64*68) * 4;   // 68608 B
    cudaFuncSetAttribute(attn64, cudaFuncAttributeMaxDynamicSharedMemorySize, smem);
    attn64<<<dim3(LSEQ/64, BATCH*NHEAD), 256, smem>>>(qP, kP, vP, aP);

    sgemm128<0><<<gGemm, 256>>>(aP, Wo, bo, out, MTOT, NFEAT, 1024);
}

// round 10
// speedup vs baseline: 2.5607x; 2.5607x over previous
#include <cuda_runtime.h>
#include <cuda_bf16.h>
#include <math.h>
#include <stdint.h>

#define BATCH 4
#define LSEQ 2048
#define NHEAD 16
#define DKH 64
#define NFEAT 1024
#define MTOT (BATCH*LSEQ)
#define MF (MTOT*NFEAT)
#define WF (NFEAT*NFEAT)

typedef __nv_bfloat16 bf16;

// ---- device scratch (allocation-free rule) ----
__device__ bf16 s_qxh[MF], s_qxl[MF], s_kxh[MF], s_kxl[MF], s_vxh[MF], s_vxl[MF];
__device__ bf16 s_wqh[WF], s_wql[WF], s_wkh[WF], s_wkl[WF];
__device__ bf16 s_wvh[WF], s_wvl[WF], s_woh[WF], s_wol[WF];
__device__ bf16 s_Qh[MF], s_Ql[MF], s_Kh[MF], s_Kl[MF], s_Vh[MF], s_Vl[MF];
__device__ bf16 s_Ah[MF], s_Al[MF];

// ---- helpers ----
__device__ __forceinline__ uint32_t smem_u32(const void* p) {
    return (uint32_t)__cvta_generic_to_shared(p);
}
__device__ __forceinline__ void cpa16(uint32_t d, const void* s) {
    asm volatile("cp.async.cg.shared.global [%0], [%1], 16;" :: "r"(d), "l"(s));
}
#define CP_COMMIT asm volatile("cp.async.commit_group;")
#define CP_WAIT0  asm volatile("cp.async.wait_group 0;")
#define CP_WAIT1  asm volatile("cp.async.wait_group 1;")

__device__ __forceinline__ void mma_bf16(float* c,
    uint32_t a0, uint32_t a1, uint32_t a2, uint32_t a3, uint32_t b0, uint32_t b1) {
    asm volatile(
        "mma.sync.aligned.m16n8k16.row.col.f32.bf16.bf16.f32 "
        "{%0,%1,%2,%3}, {%4,%5,%6,%7}, {%8,%9}, {%0,%1,%2,%3};"
        : "+f"(c[0]), "+f"(c[1]), "+f"(c[2]), "+f"(c[3])
        : "r"(a0), "r"(a1), "r"(a2), "r"(a3), "r"(b0), "r"(b1));
}
__device__ __forceinline__ void ldm4(uint32_t* r, uint32_t a) {
    asm volatile("ldmatrix.sync.aligned.m8n8.x4.shared.b16 {%0,%1,%2,%3}, [%4];"
        : "=r"(r[0]), "=r"(r[1]), "=r"(r[2]), "=r"(r[3]) : "r"(a));
}
__device__ __forceinline__ void ldm4t(uint32_t* r, uint32_t a) {
    asm volatile("ldmatrix.sync.aligned.m8n8.x4.trans.shared.b16 {%0,%1,%2,%3}, [%4];"
        : "=r"(r[0]), "=r"(r[1]), "=r"(r[2]), "=r"(r[3]) : "r"(a));
}
__device__ __forceinline__ void split2(float a, float b,
                                       __nv_bfloat162& h2, __nv_bfloat162& l2) {
    h2 = __floats2bfloat162_rn(a, b);
    l2 = __floats2bfloat162_rn(a - __bfloat162float(h2.x),
                               b - __bfloat162float(h2.y));
}

// ---------------------------------------------------------------------------
// prep: split fp32 -> bf16 hi/lo
// ---------------------------------------------------------------------------
__global__ __launch_bounds__(256)
void ksplit(const float4* __restrict__ x, bf16* __restrict__ h, bf16* __restrict__ l) {
    int i = blockIdx.x * 256 + threadIdx.x;
    float4 v = x[i];
    __nv_bfloat162 h01, l01, h23, l23;
    split2(v.x, v.y, h01, l01);
    split2(v.z, v.w, h23, l23);
    ((__nv_bfloat162*)h)[2*i]   = h01;
    ((__nv_bfloat162*)h)[2*i+1] = h23;
    ((__nv_bfloat162*)l)[2*i]   = l01;
    ((__nv_bfloat162*)l)[2*i+1] = l23;
}

// ---------------------------------------------------------------------------
// prep: Wt[n][k] = W[k][n], split hi/lo
// ---------------------------------------------------------------------------
__global__ __launch_bounds__(256)
void ktransplit(const float* __restrict__ W, bf16* __restrict__ Wth, bf16* __restrict__ Wtl) {
    __shared__ float ts[32][33];
    const int n0 = blockIdx.x * 32, k0 = blockIdx.y * 32;
    const int tx = threadIdx.x, ty = threadIdx.y;  // 32 x 8
#pragma unroll
    for (int j = 0; j < 4; j++)
        ts[ty + 8*j][tx] = W[(size_t)(k0 + ty + 8*j) * NFEAT + n0 + tx];
    __syncthreads();
#pragma unroll
    for (int j = 0; j < 4; j++) {
        float v = ts[tx][ty + 8*j];
        bf16 h = __float2bfloat16_rn(v);
        bf16 l = __float2bfloat16_rn(v - __bfloat162float(h));
        size_t idx = (size_t)(n0 + ty + 8*j) * NFEAT + k0 + tx;
        Wth[idx] = h; Wtl[idx] = l;
    }
}

// ---------------------------------------------------------------------------
// 3xBF16 GEMM: C = (Ah+Al)(Bh+Bl)^T + bias.  A [M][K] hi/lo, B = Wt [N][K] hi/lo.
// Block 128x128, BK=32, 8 warps (4m x 2n) of 32x64. cp.async double buffer.
// smem rows 40 bf16 (80B) -> conflict-free ldmatrix.
// MODE 0: fp32 out [M][N].  MODE 1: split bf16 out in [B,H,L,Dk] (scale applied).
// ---------------------------------------------------------------------------
#define GST 40
#define GSTAGE 5120                  // elems of one array per buffer
#define GSMEM_BYTES (8*GSTAGE*2)     // 81920

template<int MODE>
__global__ __launch_bounds__(256, 2)
void gemm3(const bf16* __restrict__ Agh, const bf16* __restrict__ Agl,
           const bf16* __restrict__ Bgh, const bf16* __restrict__ Bgl,
           const float* __restrict__ bias,
           float* __restrict__ Cf, bf16* __restrict__ Ch, bf16* __restrict__ Cl,
           float scale) {
    extern __shared__ bf16 sm[];
    const int t = threadIdx.x;
    const int w = t >> 5, lane = t & 31, g = lane >> 2, tig = lane & 3;
    const int mi = lane >> 3, r8 = lane & 7;
    const int wm = (w & 3) * 32, wn = (w >> 2) * 64;
    const int m0 = blockIdx.y * 128, n0 = blockIdx.x * 128;
    const uint32_t smb = smem_u32(sm);
    const int APAT = ((mi & 1) * 8 + r8) * (GST*2) + (mi >> 1) * 16;
    const int BPAT = ((mi >> 1) * 8 + r8) * (GST*2) + (mi & 1) * 16;

    const bf16* Abh = Agh + (size_t)m0 * NFEAT;
    const bf16* Abl = Agl + (size_t)m0 * NFEAT;
    const bf16* Bbh = Bgh + (size_t)n0 * NFEAT;
    const bf16* Bbl = Bgl + (size_t)n0 * NFEAT;

    float acc[2][8][4];
#pragma unroll
    for (int mt = 0; mt < 2; mt++)
#pragma unroll
        for (int nt = 0; nt < 8; nt++)
#pragma unroll
            for (int r = 0; r < 4; r++) acc[mt][nt][r] = 0.f;

    auto stage = [&](int s) {
        const int kk = s * 32;
        const uint32_t boff = (uint32_t)(s & 1) * (GSTAGE*2);
#pragma unroll
        for (int j = 0; j < 2; j++) {
            int i = t + j * 256;
            int row = i >> 2, c = i & 3;
            size_t go = (size_t)row * NFEAT + kk + c * 8;
            uint32_t d = smb + boff + (uint32_t)(row * GST + c * 8) * 2;
            cpa16(d,           Abh + go);
            cpa16(d + 10240*2, Abl + go);
            cpa16(d + 20480*2, Bbh + go);
            cpa16(d + 30720*2, Bbl + go);
        }
        CP_COMMIT;
    };

    stage(0);
    const int NS = NFEAT / 32;
    for (int s = 0; s < NS; s++) {
        if (s + 1 < NS) { stage(s + 1); CP_WAIT1; }
        else            { CP_WAIT0; }
        __syncthreads();

        const uint32_t Ab = smb + (uint32_t)(s & 1) * (GSTAGE*2);
        const uint32_t Bb = Ab + 20480*2;

#pragma unroll
        for (int kc = 0; kc < 2; kc++) {
            uint32_t ah[2][4], al[2][4];
#pragma unroll
            for (int mt = 0; mt < 2; mt++) {
                uint32_t base = Ab + (wm + mt*16) * (GST*2) + kc*32 + APAT;
                ldm4(ah[mt], base);
                ldm4(al[mt], base + 10240*2);
            }
#pragma unroll
            for (int ntp = 0; ntp < 4; ntp++) {
                uint32_t bb = Bb + (wn + ntp*16) * (GST*2) + kc*32 + BPAT;
                uint32_t bhf[4], blf[4];
                ldm4(bhf, bb);
                ldm4(blf, bb + 10240*2);
#pragma unroll
                for (int mt = 0; mt < 2; mt++) {
                    float* c0 = acc[mt][2*ntp];
                    float* c1 = acc[mt][2*ntp+1];
                    mma_bf16(c0, ah[mt][0],ah[mt][1],ah[mt][2],ah[mt][3], bhf[0],bhf[1]);
                    mma_bf16(c0, ah[mt][0],ah[mt][1],ah[mt][2],ah[mt][3], blf[0],blf[1]);
                    mma_bf16(c0, al[mt][0],al[mt][1],al[mt][2],al[mt][3], bhf[0],bhf[1]);
                    mma_bf16(c1, ah[mt][0],ah[mt][1],ah[mt][2],ah[mt][3], bhf[2],bhf[3]);
                    mma_bf16(c1, ah[mt][0],ah[mt][1],ah[mt][2],ah[mt][3], blf[2],blf[3]);
                    mma_bf16(c1, al[mt][0],al[mt][1],al[mt][2],al[mt][3], bhf[2],bhf[3]);
                }
            }
        }
        __syncthreads();
    }

#pragma unroll
    for (int mt = 0; mt < 2; mt++) {
        int r0 = m0 + wm + mt*16 + g;
#pragma unroll
        for (int nt = 0; nt < 8; nt++) {
            int col = n0 + wn + nt*8 + 2*tig;
            float2 bv = *(const float2*)(bias + col);
            float c0 = (acc[mt][nt][0] + bv.x) * scale;
            float c1 = (acc[mt][nt][1] + bv.y) * scale;
            float c2 = (acc[mt][nt][2] + bv.x) * scale;
            float c3 = (acc[mt][nt][3] + bv.y) * scale;
            if (MODE == 0) {
                *(float2*)(Cf + (size_t)r0 * NFEAT + col)     = make_float2(c0, c1);
                *(float2*)(Cf + (size_t)(r0+8) * NFEAT + col) = make_float2(c2, c3);
            } else {
                int h = col >> 6, d = col & 63;
                int b0i = r0 >> 11, l0i = r0 & 2047;
                int r1 = r0 + 8, b1i = r1 >> 11, l1i = r1 & 2047;
                size_t i0 = ((size_t)(b0i*NHEAD + h) * LSEQ + l0i) * DKH + d;
                size_t i1 = ((size_t)(b1i*NHEAD + h) * LSEQ + l1i) * DKH + d;
                __nv_bfloat162 h2, l2;
                split2(c0, c1, h2, l2);
                *(__nv_bfloat162*)(Ch + i0) = h2;
                *(__nv_bfloat162*)(Cl + i0) = l2;
                split2(c2, c3, h2, l2);
                *(__nv_bfloat162*)(Ch + i1) = h2;
                *(__nv_bfloat162*)(Cl + i1) = l2;
            }
        }
    }
}

// ---------------------------------------------------------------------------
// 3xBF16 flash attention. Block = 128 q-rows, 8 warps x 16 rows, 64-token KV
// tiles, double-buffered via cp.async. Q-frags hoisted; Ps reuses Qs region.
// Row stride 144B -> conflict-free ldmatrix. Q arrives pre-scaled by 1/8.
// ---------------------------------------------------------------------------
#define ARS 144
#define QPL_E 9216
#define KVBASE_E 18432
#define KVSTAGE_E 18432
#define ASMEM_BYTES ((KVBASE_E + 2*KVSTAGE_E) * 2)   // 110592

__global__ __launch_bounds__(256, 1)
void attn3(const bf16* __restrict__ Qh, const bf16* __restrict__ Ql,
           const bf16* __restrict__ Kh, const bf16* __restrict__ Kl,
           const bf16* __restrict__ Vh, const bf16* __restrict__ Vl,
           bf16* __restrict__ Oh, bf16* __restrict__ Ol) {
    extern __shared__ bf16 sm[];
    const int t = threadIdx.x;
    const int w = t >> 5, lane = t & 31, g = lane >> 2, tig = lane & 3;
    const int mi = lane >> 3, r8 = lane & 7;
    const int bh = blockIdx.y, q0 = blockIdx.x * 128, qrow = w * 16;
    const uint32_t smb = smem_u32(sm);
    const int APAT = ((mi & 1) * 8 + r8) * ARS + (mi >> 1) * 16;
    const int BPAT = ((mi >> 1) * 8 + r8) * ARS + (mi & 1) * 16;

    const size_t bo = (size_t)bh * LSEQ * DKH;
    const bf16 *Qhg = Qh + bo, *Qlg = Ql + bo;
    const bf16 *Khg = Kh + bo, *Klg = Kl + bo, *Vhg = Vh + bo, *Vlg = Vl + bo;

    // stage Q hi/lo
#pragma unroll
    for (int j = 0; j < 8; j++) {
        int i = t + j * 256;
        int arr = i >> 10, rem = i & 1023, row = rem >> 3, c = rem & 7;
        const bf16* src = (arr ? Qlg : Qhg) + (size_t)(q0 + row) * DKH + c * 8;
        cpa16(smb + (arr ? QPL_E*2 : 0) + (uint32_t)(row * ARS + c * 16), src);
    }
    CP_COMMIT;

    auto kvstage = [&](int kt) {
        uint32_t sb = smb + (KVBASE_E + (kt & 1) * KVSTAGE_E) * 2;
        size_t toff = (size_t)kt * 64 * DKH;
#pragma unroll
        for (int j = 0; j < 8; j++) {
            int i = t + j * 256;
            int arr = i >> 9, rem = i & 511, row = rem >> 3, c = rem & 7;
            const bf16* base = (arr == 0) ? Khg : (arr == 1) ? Klg : (arr == 2) ? Vhg : Vlg;
            cpa16(sb + (uint32_t)(arr * 4608 * 2 + row * ARS + c * 16),
                  base + toff + row * DKH + c * 8);
        }
        CP_COMMIT;
    };
    kvstage(0);
    CP_WAIT1;            // Q complete
    __syncthreads();

    // hoist this warp's Q fragments (16 rows x 64 dims, hi+lo)
    uint32_t qa[4][4], ql[4][4];
#pragma unroll
    for (int kc = 0; kc < 4; kc++) {
        uint32_t base = smb + qrow * ARS + kc * 32 + APAT;
        ldm4(qa[kc], base);
        ldm4(ql[kc], base + QPL_E*2);
    }
    __syncthreads();

    float o[8][4];
#pragma unroll
    for (int nt = 0; nt < 8; nt++)
#pragma unroll
        for (int r = 0; r < 4; r++) o[nt][r] = 0.f;
    float m0v = -1e30f, m1v = -1e30f, lsum0 = 0.f, lsum1 = 0.f;

    const int NT = LSEQ / 64;
    for (int kt = 0; kt < NT; kt++) {
        if (kt + 1 < NT) { kvstage(kt + 1); CP_WAIT1; }
        else             { CP_WAIT0; }
        __syncthreads();

        const uint32_t Kb = smb + (KVBASE_E + (kt & 1) * KVSTAGE_E) * 2;
        const uint32_t Vb = Kb + 9216 * 2;

        // ---- S = Q K^T ----
        float sc[8][4];
#pragma unroll
        for (int nt = 0; nt < 8; nt++)
#pragma unroll
            for (int r = 0; r < 4; r++) sc[nt][r] = 0.f;

#pragma unroll
        for (int kc = 0; kc < 4; kc++) {
#pragma unroll
            for (int ntp = 0; ntp < 4; ntp++) {
                uint32_t kb = Kb + ntp * 16 * ARS + kc * 32 + BPAT;
                uint32_t bhf[4], blf[4];
                ldm4(bhf, kb);
                ldm4(blf, kb + 4608*2);
                float* c0 = sc[2*ntp];
                float* c1 = sc[2*ntp+1];
                mma_bf16(c0, qa[kc][0],qa[kc][1],qa[kc][2],qa[kc][3], bhf[0],bhf[1]);
                mma_bf16(c0, qa[kc][0],qa[kc][1],qa[kc][2],qa[kc][3], blf[0],blf[1]);
                mma_bf16(c0, ql[kc][0],ql[kc][1],ql[kc][2],ql[kc][3], bhf[0],bhf[1]);
                mma_bf16(c1, qa[kc][0],qa[kc][1],qa[kc][2],qa[kc][3], bhf[2],bhf[3]);
                mma_bf16(c1, qa[kc][0],qa[kc][1],qa[kc][2],qa[kc][3], blf[2],blf[3]);
                mma_bf16(c1, ql[kc][0],ql[kc][1],ql[kc][2],ql[kc][3], bhf[2],bhf[3]);
            }
        }

        // ---- online softmax (rows qrow+g, qrow+g+8) ----
        float mx0 = -1e30f, mx1 = -1e30f;
#pragma unroll
        for (int nt = 0; nt < 8; nt++) {
            mx0 = fmaxf(mx0, fmaxf(sc[nt][0], sc[nt][1]));
            mx1 = fmaxf(mx1, fmaxf(sc[nt][2], sc[nt][3]));
        }
        mx0 = fmaxf(mx0, __shfl_xor_sync(0xffffffffu, mx0, 1));
        mx0 = fmaxf(mx0, __shfl_xor_sync(0xffffffffu, mx0, 2));
        mx1 = fmaxf(mx1, __shfl_xor_sync(0xffffffffu, mx1, 1));
        mx1 = fmaxf(mx1, __shfl_xor_sync(0xffffffffu, mx1, 2));

        float mn0 = fmaxf(m0v, mx0), mn1 = fmaxf(m1v, mx1);
        float cr0 = __expf(m0v - mn0), cr1 = __expf(m1v - mn1);
        m0v = mn0; m1v = mn1;

        float s0 = 0.f, s1 = 0.f;
#pragma unroll
        for (int nt = 0; nt < 8; nt++) {
            float p00 = __expf(sc[nt][0] - mn0);
            float p01 = __expf(sc[nt][1] - mn0);
            float p10 = __expf(sc[nt][2] - mn1);
            float p11 = __expf(sc[nt][3] - mn1);
            s0 += p00 + p01; s1 += p10 + p11;
            o[nt][0] *= cr0; o[nt][1] *= cr0;
            o[nt][2] *= cr1; o[nt][3] *= cr1;
            __nv_bfloat162 h2, l2;
            uint32_t off0 = (qrow + g) * ARS + (nt*8 + 2*tig) * 2;
            uint32_t off1 = (qrow + g + 8) * ARS + (nt*8 + 2*tig) * 2;
            split2(p00, p01, h2, l2);
            *(__nv_bfloat162*)((char*)sm + off0)           = h2;
            *(__nv_bfloat162*)((char*)sm + QPL_E*2 + off0) = l2;
            split2(p10, p11, h2, l2);
            *(__nv_bfloat162*)((char*)sm + off1)           = h2;
            *(__nv_bfloat162*)((char*)sm + QPL_E*2 + off1) = l2;
        }
        s0 += __shfl_xor_sync(0xffffffffu, s0, 1);
        s0 += __shfl_xor_sync(0xffffffffu, s0, 2);
        s1 += __shfl_xor_sync(0xffffffffu, s1, 1);
        s1 += __shfl_xor_sync(0xffffffffu, s1, 2);
        lsum0 = lsum0 * cr0 + s0;
        lsum1 = lsum1 * cr1 + s1;
        __syncwarp();   // P rows written/read only by this warp

        // ---- O += P V  (V via ldmatrix.trans) ----
#pragma unroll
        for (int kc = 0; kc < 4; kc++) {
            uint32_t pb = smb + qrow * ARS + kc * 32 + APAT;
            uint32_t pa[4], pl[4];
            ldm4(pa, pb);
            ldm4(pl, pb + QPL_E*2);
#pragma unroll
            for (int ntp = 0; ntp < 4; ntp++) {
                uint32_t vb = Vb + kc * 16 * ARS + ntp * 32 + APAT;
                uint32_t vh4[4], vl4[4];
                ldm4t(vh4, vb);
                ldm4t(vl4, vb + 4608*2);
                float* c0 = o[2*ntp];
                float* c1 = o[2*ntp+1];
                mma_bf16(c0, pa[0],pa[1],pa[2],pa[3], vh4[0],vh4[1]);
                mma_bf16(c0, pa[0],pa[1],pa[2],pa[3], vl4[0],vl4[1]);
                mma_bf16(c0, pl[0],pl[1],pl[2],pl[3], vh4[0],vh4[1]);
                mma_bf16(c1, pa[0],pa[1],pa[2],pa[3], vh4[2],vh4[3]);
                mma_bf16(c1, pa[0],pa[1],pa[2],pa[3], vl4[2],vl4[3]);
                mma_bf16(c1, pl[0],pl[1],pl[2],pl[3], vh4[2],vh4[3]);
            }
        }
        __syncthreads();
    }

    // epilogue: normalize, split, write [B,L,F] hi/lo
    float inv0 = 1.f / lsum0, inv1 = 1.f / lsum1;
    const int b = bh >> 4, h = bh & 15;
    const int r0 = q0 + qrow + g, r1 = r0 + 8;
#pragma unroll
    for (int nt = 0; nt < 8; nt++) {
        int d = h * DKH + nt*8 + 2*tig;
        size_t i0 = ((size_t)(b * LSEQ + r0)) * NFEAT + d;
        size_t i1 = ((size_t)(b * LSEQ + r1)) * NFEAT + d;
        __nv_bfloat162 h2, l2;
        split2(o[nt][0] * inv0, o[nt][1] * inv0, h2, l2);
        *(__nv_bfloat162*)(Oh + i0) = h2;
        *(__nv_bfloat162*)(Ol + i0) = l2;
        split2(o[nt][2] * inv1, o[nt][3] * inv1, h2, l2);
        *(__nv_bfloat162*)(Oh + i1) = h2;
        *(__nv_bfloat162*)(Ol + i1) = l2;
    }
}

// ---------------------------------------------------------------------------
extern "C" void kernel_launch(void* const* d_in, const int* in_sizes, int n_in,
                              void* d_out, int out_size) {
    const float* query = (const float*)d_in[0];
    const float* key_  = (const float*)d_in[1];
    const float* value = (const float*)d_in[2];
    const float* Wq = (const float*)d_in[3];
    const float* bq = (const float*)d_in[4];
    const float* Wk = (const float*)d_in[5];
    const float* bk = (const float*)d_in[6];
    const float* Wv = (const float*)d_in[7];
    const float* bv = (const float*)d_in[8];
    const float* Wo = (const float*)d_in[9];
    const float* bo = (const float*)d_in[10];
    float* out = (float*)d_out;

#define SYM(p, s) bf16* p; cudaGetSymbolAddress((void**)&p, s)
    SYM(qxh, s_qxh); SYM(qxl, s_qxl); SYM(kxh, s_kxh); SYM(kxl, s_kxl);
    SYM(vxh, s_vxh); SYM(vxl, s_vxl);
    SYM(wqh, s_wqh); SYM(wql, s_wql); SYM(wkh, s_wkh); SYM(wkl, s_wkl);
    SYM(wvh, s_wvh); SYM(wvl, s_wvl); SYM(woh, s_woh); SYM(wol, s_wol);
    SYM(Qh, s_Qh); SYM(Ql, s_Ql); SYM(Kh, s_Kh); SYM(Kl, s_Kl);
    SYM(Vh, s_Vh); SYM(Vl, s_Vl); SYM(Ah, s_Ah); SYM(Al, s_Al);
#undef SYM

    // prep: split activations, transpose+split weights
    ksplit<<<MF/1024, 256>>>((const float4*)query, qxh, qxl);
    ksplit<<<MF/1024, 256>>>((const float4*)key_,  kxh, kxl);
    ksplit<<<MF/1024, 256>>>((const float4*)value, vxh, vxl);
    dim3 tg(32, 32), tb(32, 8);
    ktransplit<<<tg, tb>>>(Wq, wqh, wql);
    ktransplit<<<tg, tb>>>(Wk, wkh, wkl);
    ktransplit<<<tg, tb>>>(Wv, wvh, wvl);
    ktransplit<<<tg, tb>>>(Wo, woh, wol);

    cudaFuncSetAttribute(gemm3<0>, cudaFuncAttributeMaxDynamicSharedMemorySize, GSMEM_BYTES);
    cudaFuncSetAttribute(gemm3<1>, cudaFuncAttributeMaxDynamicSharedMemorySize, GSMEM_BYTES);
    cudaFuncSetAttribute(attn3, cudaFuncAttributeMaxDynamicSharedMemorySize, ASMEM_BYTES);

    dim3 gg(NFEAT/128, MTOT/128);   // (8, 64)
    // QKV projections -> split bf16 in [B,H,L,Dk]; Q pre-scaled by 1/sqrt(Dk)=0.125
    gemm3<1><<<gg, 256, GSMEM_BYTES>>>(qxh, qxl, wqh, wql, bq, nullptr, Qh, Ql, 0.125f);
    gemm3<1><<<gg, 256, GSMEM_BYTES>>>(kxh, kxl, wkh, wkl, bk, nullptr, Kh, Kl, 1.0f);
    gemm3<1><<<gg, 256, GSMEM_BYTES>>>(vxh, vxl, wvh, wvl, bv, nullptr, Vh, Vl, 1.0f);

    attn3<<<dim3(LSEQ/128, BATCH*NHEAD), 256, ASMEM_BYTES>>>(Qh, Ql, Kh, Kl, Vh, Vl, Ah, Al);

    // output projection -> fp32 result
    gemm3<0><<<gg, 256, GSMEM_BYTES>>>(Ah, Al, woh, wol, bo, out, nullptr, nullptr, 1.0f);
}